// round 15
// baseline (speedup 1.0000x reference)
#include <cuda_runtime.h>

// YOLO v1 loss (reference-bug-compatible), single fused kernel.
//   predictions: [N, 49*30] f32  (per cell: 20 class, b1[x,y,w,h,c], b2[x,y,w,h,c])
//   targets:     [N, 49*25] f32  (per cell: 20 class, flag, box_rest[4])
//   tbox = targets[cell][20:25] -> (flag, bx, by, bw, bh); flag acts as "x" in IoU/xy.
//   obj  = (flag == 1.0f)
// out[0] = (sum obj*(coord+conf+cls) + 0.5*sum (1-obj)*(b1c^2+b2c^2)) / N
//
// R12 data: two-launch version = 75.4 us, of which yolo_reduce = 6.24 us pure
// overhead. This version fuses the final reduction via a last-block-done
// counter (deterministic: fixed-order sum by the last block; counter reset
// each run -> graph-replay safe; partials read with __ldcg to bypass L1) and
// uses a persistent grid (7 blocks/SM, grid-stride over tiles) to amortize
// CTA churn and cut partials 6272 -> 1036.
//
// Staging layout unchanged: coalesced float2/float4 LDG -> smem, pred
// re-strided 30->31 so compute-phase LDS is bank-conflict-free.

#define NCLS       20
#define PRED_CH    30
#define PRED_PAD   31
#define TGT_CH     25
#define SS_CELLS   49
#define LAMBDA_COORD 5.0f
#define LAMBDA_NOOBJ 0.5f
#define IOU_EPS    1e-6f

#define TPB        128
#define TILE       128
#define PERSIST_BLOCKS (148 * 7)   // 1036
#define MAX_BLOCKS 8192

__device__ float        g_partials[MAX_BLOCKS];
__device__ unsigned int g_done = 0;

__device__ __forceinline__ float iou_mid(float ax, float ay, float aw, float ah,
                                         float bx, float by, float bw, float bh) {
    float ax1 = ax - aw * 0.5f, ay1 = ay - ah * 0.5f;
    float ax2 = ax + aw * 0.5f, ay2 = ay + ah * 0.5f;
    float bx1 = bx - bw * 0.5f, by1 = by - bh * 0.5f;
    float bx2 = bx + bw * 0.5f, by2 = by + bh * 0.5f;
    float iw = fmaxf(fminf(ax2, bx2) - fmaxf(ax1, bx1), 0.0f);
    float ih = fmaxf(fminf(ay2, by2) - fmaxf(ay1, by1), 0.0f);
    float inter  = iw * ih;
    float area_a = fabsf((ax2 - ax1) * (ay2 - ay1));
    float area_b = fabsf((bx2 - bx1) * (by2 - by1));
    return inter / (area_a + area_b - inter + IOU_EPS);
}

__global__ void __launch_bounds__(TPB)
yolo_fused(const float* __restrict__ pred, const float* __restrict__ tgt,
           float* __restrict__ out, int total_cells, int ntiles, float inv_n) {
    __shared__ float sp[TILE * PRED_PAD];   // 15872 B, stride 31 -> conflict-free LDS
    __shared__ float st[TILE * TGT_CH];     // 12800 B, stride 25 (odd) -> conflict-free LDS
    __shared__ float sh[TPB / 32];
    __shared__ unsigned int sh_is_last;

    const int tid = threadIdx.x;
    float acc = 0.0f;

    for (int tile = blockIdx.x; tile < ntiles; tile += gridDim.x) {
        const int base_cell = tile * TILE;

        // ---- stage predictions: coalesced float2 LDG, re-stride 30 -> 31 ----
        {
            const float*  gp  = pred + (size_t)base_cell * PRED_CH;
            const float2* gp2 = reinterpret_cast<const float2*>(gp);
            const int limit = (total_cells - base_cell) * PRED_CH;
#pragma unroll 8
            for (int i4 = tid; i4 < TILE * PRED_CH / 2; i4 += TPB) {
                int i = i4 * 2;
                float2 v;
                if (i + 1 < limit) {
                    v = gp2[i4];
                } else {                  // tail tile only (unused when cells % 128 == 0)
                    v.x = (i     < limit) ? gp[i]     : 0.0f;
                    v.y = (i + 1 < limit) ? gp[i + 1] : 0.0f;
                }
                unsigned c  = (unsigned)i / PRED_CH;
                unsigned ch = (unsigned)i - c * PRED_CH;     // even, ch+1 <= 29
                sp[c * PRED_PAD + ch]     = v.x;
                sp[c * PRED_PAD + ch + 1] = v.y;
            }
        }
        // ---- stage targets: coalesced float4 identity copy ----
        {
            const float* gt = tgt + (size_t)base_cell * TGT_CH;
            const int limit = (total_cells - base_cell) * TGT_CH;
            const float4* gt4 = reinterpret_cast<const float4*>(gt);
            float4* st4 = reinterpret_cast<float4*>(st);
#pragma unroll
            for (int i4 = tid; i4 < TILE * TGT_CH / 4; i4 += TPB) {
                int e = i4 * 4;
                if (e + 3 < limit) {
                    st4[i4] = gt4[i4];
                } else {                  // tail tile only
                    float4 v;
                    v.x = (e + 0 < limit) ? gt[e + 0] : 0.0f;
                    v.y = (e + 1 < limit) ? gt[e + 1] : 0.0f;
                    v.z = (e + 2 < limit) ? gt[e + 2] : 0.0f;
                    v.w = (e + 3 < limit) ? gt[e + 3] : 0.0f;
                    st4[i4] = v;
                }
            }
        }
        __syncthreads();

        // ---- per-thread cell compute from smem (bank-conflict-free) ----
        const int cell = base_cell + tid;
        if (cell < total_cells) {
            const float* P = &sp[tid * PRED_PAD];
            const float* T = &st[tid * TGT_CH];

            float cls = 0.0f;
#pragma unroll
            for (int i = 0; i < NCLS; i++) {
                float d = P[i] - T[i];
                cls = fmaf(d, d, cls);
            }

            float b1x = P[20], b1y = P[21], b1w = P[22], b1h = P[23], b1c = P[24];
            float b2x = P[25], b2y = P[26], b2w = P[27], b2h = P[28], b2c = P[29];

            float tb0 = T[20];  // flag (reference uses it as the "x" coordinate)
            float tb1 = T[21], tb2 = T[22], tb3 = T[23], tb4 = T[24];

            float obj = (tb0 == 1.0f) ? 1.0f : 0.0f;

            float iou1 = iou_mid(b1x, b1y, b1w, b1h, tb0, tb1, tb2, tb3);
            float iou2 = iou_mid(b2x, b2y, b2w, b2h, tb0, tb1, tb2, tb3);

            bool sel = iou1 > iou2;             // tie -> b2 (matches jnp.where)
            float rx = sel ? b1x : b2x;
            float ry = sel ? b1y : b2y;
            float rw = sel ? b1w : b2w;
            float rh = sel ? b1h : b2h;
            float rc = sel ? b1c : b2c;

            float dx = rx - tb0, dy = ry - tb1;
            float xy = dx * dx + dy * dy;
            float dw = sqrtf(rw) - sqrtf(tb2);
            float dh = sqrtf(rh) - sqrtf(tb3);
            float wh = dw * dw + dh * dh;
            float coord = LAMBDA_COORD * (xy + wh);
            float dc = rc - tb4;
            float conf = dc * dc;

            acc += obj * (coord + conf + cls)
                 + LAMBDA_NOOBJ * (1.0f - obj) * (b1c * b1c + b2c * b2c);
        }
        __syncthreads();   // smem reuse guard before next tile's staging
    }

    // ---- deterministic block reduction ----
    int lane = tid & 31;
    int wid  = tid >> 5;
#pragma unroll
    for (int o = 16; o > 0; o >>= 1)
        acc += __shfl_down_sync(0xffffffffu, acc, o);
    if (lane == 0) sh[wid] = acc;
    __syncthreads();
    if (wid == 0) {
        float v = (lane < TPB / 32) ? sh[lane] : 0.0f;
#pragma unroll
        for (int o = 16; o > 0; o >>= 1)
            v += __shfl_down_sync(0xffffffffu, v, o);
        if (lane == 0) g_partials[blockIdx.x] = v;
    }
    __syncthreads();

    // ---- last-block-done fused final reduction (deterministic fixed order) ----
    if (tid == 0) {
        __threadfence();
        unsigned v = atomicAdd(&g_done, 1u);
        sh_is_last = (v == gridDim.x - 1) ? 1u : 0u;
    }
    __syncthreads();
    if (sh_is_last) {
        float s = 0.0f;
        for (int i = tid; i < (int)gridDim.x; i += TPB)
            s += __ldcg(&g_partials[i]);     // L2-scope read: other SMs' writes
#pragma unroll
        for (int o = 16; o > 0; o >>= 1)
            s += __shfl_down_sync(0xffffffffu, s, o);
        if (lane == 0) sh[wid] = s;
        __syncthreads();
        if (wid == 0) {
            float v2 = (lane < TPB / 32) ? sh[lane] : 0.0f;
#pragma unroll
            for (int o = 16; o > 0; o >>= 1)
                v2 += __shfl_down_sync(0xffffffffu, v2, o);
            if (lane == 0) {
                out[0] = v2 * inv_n;
                g_done = 0;              // reset for next graph replay
            }
        }
    }
}

extern "C" void kernel_launch(void* const* d_in, const int* in_sizes, int n_in,
                              void* d_out, int out_size) {
    const float* pred = (const float*)d_in[0];
    const float* tgt  = (const float*)d_in[1];

    int total_cells = in_sizes[0] / PRED_CH;   // N * 49 = 802816 for N=16384
    int N           = total_cells / SS_CELLS;
    int ntiles      = (total_cells + TILE - 1) / TILE;   // 6272 for N=16384

    int grid = ntiles < PERSIST_BLOCKS ? ntiles : PERSIST_BLOCKS;   // 1036 persistent
    if (grid > MAX_BLOCKS) grid = MAX_BLOCKS;

    yolo_fused<<<grid, TPB>>>(pred, tgt, (float*)d_out,
                              total_cells, ntiles, 1.0f / (float)N);
}